// round 12
// baseline (speedup 1.0000x reference)
#include <cuda_runtime.h>
#include <cstdint>

// Problem geometry
#define CB_K 512
#define CB_C 64
#define HW   4096                     // 64*64 pixels per (b,t) plane
#define N_PIX  524288
#define Q_ELEMS 33554432
#define OFF_IDX  Q_ELEMS
#define OFF_LOSS (OFF_IDX + N_PIX)
#define OFF_ENT  (OFF_LOSS + 1)

// Persistent config: 148 CTAs (1/SM), 256 threads, equal pixel split
#define THREADS 256
#define NCTAS   148
#define ESTRIDE 516                   // padded floats per channel row of codebook
#define SMEM_FLOATS (CB_C * ESTRIDE)  // 33024 floats
#define SMEM_BYTES (SMEM_FLOATS*4 + CB_K*4 /*E*/ + CB_K*4 /*hist*/ + 4*4 /*lane_sum*/)

typedef unsigned long long u64;
typedef unsigned int u32;

__device__ double   g_lane[4] = {0.0, 0.0, 0.0, 0.0};
__device__ int      g_counts[CB_K] = {};
__device__ unsigned g_ticket = 0u;

__global__ void __launch_bounds__(THREADS, 1)
vq_main(const float* __restrict__ x, const float* __restrict__ cb, float* __restrict__ out) {
    extern __shared__ float smem[];
    float* es   = smem;                       // codebook transposed [c][k], stride 516
    float* ee   = smem + SMEM_FLOATS;         // E_k (fp32 sequential fma, reference chain)
    int*   hist = (int*)(ee + CB_K);          // per-CTA histogram (whole CTA lifetime)
    float* lane_sum = (float*)(hist + CB_K);  // per-CTA loss partials by (index mod 4)

    const int tid = threadIdx.x;

    // ---- one-time staging per CTA (persistent: amortized over ~7 tiles) ----
    for (int i = tid; i < CB_K * CB_C; i += THREADS) {
        int k = i >> 6, c = i & 63;
        es[c * ESTRIDE + k] = cb[i];
    }
    for (int k = tid; k < CB_K; k += THREADS) hist[k] = 0;
    if (tid < 4) lane_sum[tid] = 0.f;
    __syncthreads();
    for (int k = tid; k < CB_K; k += THREADS) {
        float s = 0.f;
        #pragma unroll
        for (int c = 0; c < CB_C; ++c) { float e = es[c * ESTRIDE + k]; s = __fmaf_rn(e, e, s); }
        ee[k] = s;
    }
    __syncthreads();

    unsigned sbase = (unsigned)__cvta_generic_to_shared(es);
    unsigned hbase = (unsigned)__cvta_generic_to_shared(ee);

    // ---- equal pixel-range split across 148 CTAs (even-aligned boundaries) ----
    const unsigned b = blockIdx.x;
    const unsigned pstart = 2u * ((b * 262144u) / 148u);
    const unsigned pend   = 2u * (((b + 1u) * 262144u) / 148u);

    for (unsigned p0 = pstart + 2u * (unsigned)tid; p0 < pend; p0 += 2u * THREADS) {
        const unsigned plane = p0 >> 12;
        const unsigned j0 = p0 & 4095u;
        const float* xp = x + (size_t)plane * (CB_C * HW) + j0;

        // two adjacent pixels per thread; all channels in registers (x read once)
        float2 f[CB_C];
        #pragma unroll
        for (int c = 0; c < CB_C; ++c) f[c] = *(const float2*)(xp + (size_t)c * HW);

        float Sa = 0.f, Sb = 0.f;
        #pragma unroll
        for (int c = 0; c < CB_C; ++c) {
            Sa = __fmaf_rn(f[c].x, f[c].x, Sa);
            Sb = __fmaf_rn(f[c].y, f[c].y, Sb);
        }

        float bestA = 3.4e38f, bestB = 3.4e38f;
        int biA = 0, biB = 0;

        // 64 tiles of 8 codes. Codes 0-5 of each tile: packed FFMA2 (rt3-banked);
        // codes 6-7: scalar FFMA interleaved into the banking gaps (rt2).
        // Every lane/scalar is the identical sequential fp32 fma chain over ascending
        // c, then the reference two-rounding: t=fl(S-2D); d=fl(t+E_k); argmin asc. k.
        #pragma unroll 1
        for (int kt = 0; kt < CB_K / 8; ++kt) {
            u64 a0 = 0, a1 = 0, a2 = 0, b0 = 0, b1 = 0, b2 = 0;
            float sA6 = 0.f, sA7 = 0.f, sB6 = 0.f, sB7 = 0.f;
            unsigned ebase = sbase + (unsigned)(kt * 32);
            #pragma unroll
            for (int c = 0; c < CB_C; ++c) {
                u64 e01, e23, e45, e67;
                unsigned ea = ebase + (unsigned)(c * (ESTRIDE * 4));
                asm volatile("ld.shared.v2.u64 {%0,%1}, [%2];"    : "=l"(e01), "=l"(e23) : "r"(ea));
                asm volatile("ld.shared.v2.u64 {%0,%1}, [%2+16];" : "=l"(e45), "=l"(e67) : "r"(ea));
                u64 fa, fb;
                asm("mov.b64 %0, {%1,%1};" : "=l"(fa) : "f"(f[c].x));
                asm("mov.b64 %0, {%1,%1};" : "=l"(fb) : "f"(f[c].y));
                asm("fma.rn.f32x2 %0, %1, %2, %0;" : "+l"(a0) : "l"(fa), "l"(e01));
                asm("fma.rn.f32x2 %0, %1, %2, %0;" : "+l"(b0) : "l"(fb), "l"(e01));
                asm("fma.rn.f32x2 %0, %1, %2, %0;" : "+l"(a1) : "l"(fa), "l"(e23));
                asm("fma.rn.f32x2 %0, %1, %2, %0;" : "+l"(b1) : "l"(fb), "l"(e23));
                asm("fma.rn.f32x2 %0, %1, %2, %0;" : "+l"(a2) : "l"(fa), "l"(e45));
                asm("fma.rn.f32x2 %0, %1, %2, %0;" : "+l"(b2) : "l"(fb), "l"(e45));
                float e6 = __uint_as_float((u32)e67);
                float e7 = __uint_as_float((u32)(e67 >> 32));
                sA6 = __fmaf_rn(f[c].x, e6, sA6);
                sB6 = __fmaf_rn(f[c].y, e6, sB6);
                sA7 = __fmaf_rn(f[c].x, e7, sA7);
                sB7 = __fmaf_rn(f[c].y, e7, sB7);
            }
            // Epilogue: E for these 8 codes; two reference roundings; streaming argmin.
            u64 h[4];
            {
                unsigned ha = hbase + (unsigned)(kt * 32);
                asm volatile("ld.shared.v2.u64 {%0,%1}, [%2];"    : "=l"(h[0]), "=l"(h[1]) : "r"(ha));
                asm volatile("ld.shared.v2.u64 {%0,%1}, [%2+16];" : "=l"(h[2]), "=l"(h[3]) : "r"(ha));
            }
            u64 av[3] = {a0, a1, a2};
            u64 bv[3] = {b0, b1, b2};
            #pragma unroll
            for (int q = 0; q < 3; ++q) {
                float elo = __uint_as_float((u32)h[q]);
                float ehi = __uint_as_float((u32)(h[q] >> 32));
                float Dal = __uint_as_float((u32)av[q]);
                float Dah = __uint_as_float((u32)(av[q] >> 32));
                float Dbl = __uint_as_float((u32)bv[q]);
                float Dbh = __uint_as_float((u32)(bv[q] >> 32));
                float dAl = __fadd_rn(__fmaf_rn(-2.f, Dal, Sa), elo);
                float dAh = __fadd_rn(__fmaf_rn(-2.f, Dah, Sa), ehi);
                float dBl = __fadd_rn(__fmaf_rn(-2.f, Dbl, Sb), elo);
                float dBh = __fadd_rn(__fmaf_rn(-2.f, Dbh, Sb), ehi);
                int k0 = kt * 8 + 2 * q;
                if (dAl < bestA) { bestA = dAl; biA = k0;     }
                if (dAh < bestA) { bestA = dAh; biA = k0 + 1; }
                if (dBl < bestB) { bestB = dBl; biB = k0;     }
                if (dBh < bestB) { bestB = dBh; biB = k0 + 1; }
            }
            {
                float e6 = __uint_as_float((u32)h[3]);
                float e7 = __uint_as_float((u32)(h[3] >> 32));
                float dA6 = __fadd_rn(__fmaf_rn(-2.f, sA6, Sa), e6);
                float dA7 = __fadd_rn(__fmaf_rn(-2.f, sA7, Sa), e7);
                float dB6 = __fadd_rn(__fmaf_rn(-2.f, sB6, Sb), e6);
                float dB7 = __fadd_rn(__fmaf_rn(-2.f, sB7, Sb), e7);
                int k0 = kt * 8 + 6;
                if (dA6 < bestA) { bestA = dA6; biA = k0;     }
                if (dA7 < bestA) { bestA = dA7; biA = k0 + 1; }
                if (dB6 < bestB) { bestB = dB6; biB = k0;     }
                if (dB7 < bestB) { bestB = dB7; biB = k0 + 1; }
            }
        }

        atomicAdd(&hist[biA], 1);
        atomicAdd(&hist[biB], 1);

        // ---- loss (XLA NEON-vec4 emulation, validated) + ST output ----
        const bool quant = (plane >= 2);
        float scaleQ = 1.f, invQ = 1.f;
        if (quant) {
            int lg = 31 - __clz((int)plane);   // 1..6
            int kq = 7 - lg;                    // 6..1
            scaleQ = (float)(1 << kq);
            invQ   = 1.f / (float)(1 << kq);
        }
        float acc0 = 0.f, acc1 = 0.f;
        float* outq = out + (size_t)plane * (CB_C * HW) + j0;
        #pragma unroll
        for (int c = 0; c < CB_C; ++c) {
            float qa = es[c * ESTRIDE + biA];
            float qb = es[c * ESTRIDE + biB];
            float da = __fsub_rn(qa, f[c].x);
            float db = __fsub_rn(qb, f[c].y);
            float v0 = __fmul_rn(da, da);
            float v1 = __fmul_rn(db, db);
            if (quant) {
                float m0 = __fsub_rn(__fmaf_rn(v0, scaleQ, 8388608.f), 8388608.f);
                float m1 = __fsub_rn(__fmaf_rn(v1, scaleQ, 8388608.f), 8388608.f);
                acc0 = __fmaf_rn(m0, invQ, acc0);
                acc1 = __fmaf_rn(m1, invQ, acc1);
            } else {
                acc0 = __fadd_rn(v0, acc0);
                acc1 = __fadd_rn(v1, acc1);
            }
            *(float2*)(outq + (size_t)c * HW) =
                make_float2(__fadd_rn(f[c].x, da), __fadd_rn(f[c].y, db));
        }
        *(float2*)(out + OFF_IDX + p0) = make_float2((float)biA, (float)biB);

        // shared fp32 atomics: quantized values are multiples of 2^-6, CTA-lane
        // totals < 2^18 -> exact; planes 0-1 within existing noise budget.
        atomicAdd(&lane_sum[p0 & 3], acc0);
        atomicAdd(&lane_sum[(p0 & 3) + 1], acc1);
    }

    // ---- per-CTA flush ----
    __syncthreads();
    if (tid < 4) atomicAdd(&g_lane[tid], (double)lane_sum[tid]);
    for (int k = tid; k < CB_K; k += THREADS) {
        int cth = hist[k];
        if (cth) atomicAdd(&g_counts[k], cth);
    }

    // ---- last-CTA finalize + self-reset (graph-replay deterministic) ----
    __shared__ unsigned is_last;
    __threadfence();
    if (tid == 0) is_last = (atomicAdd(&g_ticket, 1u) == NCTAS - 1u) ? 1u : 0u;
    __syncthreads();
    if (is_last) {
        __threadfence();
        double e = 0.0;
        for (int k = tid; k < CB_K; k += THREADS) {
            int c = g_counts[k];
            if (c) { double p = (double)c / (double)N_PIX; e -= p * log2(p); }
            g_counts[k] = 0;
        }
        double* red = (double*)smem;   // es region dead; 16B-aligned
        red[tid] = e;
        __syncthreads();
        for (int o = THREADS / 2; o > 0; o >>= 1) {
            if (tid < o) red[tid] += red[tid + o];
            __syncthreads();
        }
        if (tid == 0) {
            out[OFF_ENT] = (float)red[0];
            // NEON faddp horizontal reduce: (s0+s1) + (s2+s3), all fp32.
            float s0 = (float)g_lane[0], s1 = (float)g_lane[1];
            float s2 = (float)g_lane[2], s3 = (float)g_lane[3];
            float hs = __fadd_rn(__fadd_rn(s0, s1), __fadd_rn(s2, s3));
            float L  = hs * (1.f / 33554432.f);
            out[OFF_LOSS] = __fadd_rn(L, 0.25f * L);
            g_lane[0] = 0.0; g_lane[1] = 0.0; g_lane[2] = 0.0; g_lane[3] = 0.0;
            g_ticket = 0u;
        }
    }
}

extern "C" void kernel_launch(void* const* d_in, const int* in_sizes, int n_in,
                              void* d_out, int out_size) {
    const float* x  = (const float*)d_in[0];
    const float* cb = (const float*)d_in[1];
    float* out = (float*)d_out;
    cudaFuncSetAttribute(vq_main, cudaFuncAttributeMaxDynamicSharedMemorySize, SMEM_BYTES);
    vq_main<<<NCTAS, THREADS, SMEM_BYTES>>>(x, cb, out);
}

// round 13
// speedup vs baseline: 1.0572x; 1.0572x over previous
#include <cuda_runtime.h>
#include <cstdint>

// Problem geometry
#define CB_K 512
#define CB_C 64
#define HW   4096                     // 64*64 pixels per (b,t) plane
#define N_PIX  524288
#define Q_ELEMS 33554432
#define OFF_IDX  Q_ELEMS
#define OFF_LOSS (OFF_IDX + N_PIX)
#define OFF_ENT  (OFF_LOSS + 1)

// Persistent config: 148 CTAs (1/SM), 256 threads, equal pixel split
#define THREADS 256
#define NCTAS   148
#define ESTRIDE 516                   // padded floats per channel row of codebook
#define SMEM_FLOATS (CB_C * ESTRIDE)  // 33024 floats
#define SMEM_BYTES (SMEM_FLOATS*4 + CB_K*4 /*E*/ + CB_K*4 /*hist*/ + 4*4 /*lane_sum*/)

typedef unsigned long long u64;
typedef unsigned int u32;

__device__ double   g_lane[4] = {0.0, 0.0, 0.0, 0.0};
__device__ int      g_counts[CB_K] = {};
__device__ unsigned g_ticket = 0u;

__global__ void __launch_bounds__(THREADS, 1)
vq_main(const float* __restrict__ x, const float* __restrict__ cb, float* __restrict__ out) {
    extern __shared__ float smem[];
    float* es   = smem;                       // codebook transposed [c][k], stride 516
    float* ee   = smem + SMEM_FLOATS;         // E_k (fp32 sequential fma, reference chain)
    int*   hist = (int*)(ee + CB_K);          // per-CTA histogram (whole CTA lifetime)
    float* lane_sum = (float*)(hist + CB_K);  // per-CTA loss partials by (index mod 4)

    const int tid = threadIdx.x;

    // ---- one-time staging per CTA (persistent: amortized over ~7 tiles) ----
    for (int i = tid; i < CB_K * CB_C; i += THREADS) {
        int k = i >> 6, c = i & 63;
        es[c * ESTRIDE + k] = cb[i];
    }
    for (int k = tid; k < CB_K; k += THREADS) hist[k] = 0;
    if (tid < 4) lane_sum[tid] = 0.f;
    __syncthreads();
    for (int k = tid; k < CB_K; k += THREADS) {
        float s = 0.f;
        #pragma unroll
        for (int c = 0; c < CB_C; ++c) { float e = es[c * ESTRIDE + k]; s = __fmaf_rn(e, e, s); }
        ee[k] = s;
    }
    __syncthreads();

    unsigned sbase = (unsigned)__cvta_generic_to_shared(es);
    unsigned hbase = (unsigned)__cvta_generic_to_shared(ee);

    // ---- equal pixel-range split across 148 CTAs (even-aligned boundaries) ----
    const unsigned b = blockIdx.x;
    const unsigned pstart = 2u * ((b * 262144u) / 148u);
    const unsigned pend   = 2u * (((b + 1u) * 262144u) / 148u);

    for (unsigned p0 = pstart + 2u * (unsigned)tid; p0 < pend; p0 += 2u * THREADS) {
        const unsigned plane = p0 >> 12;
        const unsigned j0 = p0 & 4095u;
        const float* xp = x + (size_t)plane * (CB_C * HW) + j0;

        // two adjacent pixels per thread; all channels in registers (x read once)
        float2 f[CB_C];
        #pragma unroll
        for (int c = 0; c < CB_C; ++c) f[c] = *(const float2*)(xp + (size_t)c * HW);

        float Sa = 0.f, Sb = 0.f;
        #pragma unroll
        for (int c = 0; c < CB_C; ++c) {
            Sa = __fmaf_rn(f[c].x, f[c].x, Sa);
            Sb = __fmaf_rn(f[c].y, f[c].y, Sb);
        }

        float bestA = 3.4e38f, bestB = 3.4e38f;
        int biA = 0, biB = 0;

        // 64 tiles of 8 codes: packed-FFMA2 sequential-fma dot (each lane = the
        // identical ascending-c fp32 fma chain), then the reference two-rounding:
        // t = fl(S - 2D); d = fl(t + E_k); argmin ascending k, strict <.
        // FFMA2s ordered in (a_i, b_i) pairs so the shared e-operand sits in the
        // same slot on back-to-back instructions (operand-reuse latch).
        #pragma unroll 1
        for (int kt = 0; kt < CB_K / 8; ++kt) {
            u64 a[4] = {0,0,0,0}, bb[4] = {0,0,0,0};
            unsigned ebase = sbase + (unsigned)(kt * 32);
            #pragma unroll
            for (int c = 0; c < CB_C; ++c) {
                u64 e0, e1, e2, e3;
                unsigned ea = ebase + (unsigned)(c * (ESTRIDE * 4));
                asm volatile("ld.shared.v2.u64 {%0,%1}, [%2];"    : "=l"(e0), "=l"(e1) : "r"(ea));
                asm volatile("ld.shared.v2.u64 {%0,%1}, [%2+16];" : "=l"(e2), "=l"(e3) : "r"(ea));
                u64 fa, fb;
                asm("mov.b64 %0, {%1,%1};" : "=l"(fa) : "f"(f[c].x));
                asm("mov.b64 %0, {%1,%1};" : "=l"(fb) : "f"(f[c].y));
                asm("fma.rn.f32x2 %0, %1, %2, %0;" : "+l"(a[0])  : "l"(fa), "l"(e0));
                asm("fma.rn.f32x2 %0, %1, %2, %0;" : "+l"(bb[0]) : "l"(fb), "l"(e0));
                asm("fma.rn.f32x2 %0, %1, %2, %0;" : "+l"(a[1])  : "l"(fa), "l"(e1));
                asm("fma.rn.f32x2 %0, %1, %2, %0;" : "+l"(bb[1]) : "l"(fb), "l"(e1));
                asm("fma.rn.f32x2 %0, %1, %2, %0;" : "+l"(a[2])  : "l"(fa), "l"(e2));
                asm("fma.rn.f32x2 %0, %1, %2, %0;" : "+l"(bb[2]) : "l"(fb), "l"(e2));
                asm("fma.rn.f32x2 %0, %1, %2, %0;" : "+l"(a[3])  : "l"(fa), "l"(e3));
                asm("fma.rn.f32x2 %0, %1, %2, %0;" : "+l"(bb[3]) : "l"(fb), "l"(e3));
            }
            u64 h[4];
            {
                unsigned ha = hbase + (unsigned)(kt * 32);
                asm volatile("ld.shared.v2.u64 {%0,%1}, [%2];"    : "=l"(h[0]), "=l"(h[1]) : "r"(ha));
                asm volatile("ld.shared.v2.u64 {%0,%1}, [%2+16];" : "=l"(h[2]), "=l"(h[3]) : "r"(ha));
            }
            #pragma unroll
            for (int q = 0; q < 4; ++q) {
                float elo = __uint_as_float((u32)h[q]);
                float ehi = __uint_as_float((u32)(h[q] >> 32));
                float Dal = __uint_as_float((u32)a[q]);
                float Dah = __uint_as_float((u32)(a[q] >> 32));
                float Dbl = __uint_as_float((u32)bb[q]);
                float Dbh = __uint_as_float((u32)(bb[q] >> 32));
                float dAl = __fadd_rn(__fmaf_rn(-2.f, Dal, Sa), elo);
                float dAh = __fadd_rn(__fmaf_rn(-2.f, Dah, Sa), ehi);
                float dBl = __fadd_rn(__fmaf_rn(-2.f, Dbl, Sb), elo);
                float dBh = __fadd_rn(__fmaf_rn(-2.f, Dbh, Sb), ehi);
                int k0 = kt * 8 + 2 * q;
                if (dAl < bestA) { bestA = dAl; biA = k0;     }
                if (dAh < bestA) { bestA = dAh; biA = k0 + 1; }
                if (dBl < bestB) { bestB = dBl; biB = k0;     }
                if (dBh < bestB) { bestB = dBh; biB = k0 + 1; }
            }
        }

        atomicAdd(&hist[biA], 1);
        atomicAdd(&hist[biB], 1);

        // ---- loss (XLA NEON-vec4 emulation, validated) + ST output ----
        const bool quant = (plane >= 2);
        float scaleQ = 1.f, invQ = 1.f;
        if (quant) {
            int lg = 31 - __clz((int)plane);   // 1..6
            int kq = 7 - lg;                    // 6..1
            scaleQ = (float)(1 << kq);
            invQ   = 1.f / (float)(1 << kq);
        }
        float acc0 = 0.f, acc1 = 0.f;
        float* outq = out + (size_t)plane * (CB_C * HW) + j0;
        #pragma unroll
        for (int c = 0; c < CB_C; ++c) {
            float qa = es[c * ESTRIDE + biA];
            float qb = es[c * ESTRIDE + biB];
            float da = __fsub_rn(qa, f[c].x);
            float db = __fsub_rn(qb, f[c].y);
            float v0 = __fmul_rn(da, da);
            float v1 = __fmul_rn(db, db);
            if (quant) {
                float m0 = __fsub_rn(__fmaf_rn(v0, scaleQ, 8388608.f), 8388608.f);
                float m1 = __fsub_rn(__fmaf_rn(v1, scaleQ, 8388608.f), 8388608.f);
                acc0 = __fmaf_rn(m0, invQ, acc0);
                acc1 = __fmaf_rn(m1, invQ, acc1);
            } else {
                acc0 = __fadd_rn(v0, acc0);
                acc1 = __fadd_rn(v1, acc1);
            }
            *(float2*)(outq + (size_t)c * HW) =
                make_float2(__fadd_rn(f[c].x, da), __fadd_rn(f[c].y, db));
        }
        *(float2*)(out + OFF_IDX + p0) = make_float2((float)biA, (float)biB);

        // shared fp32 atomics: quantized values are multiples of 2^-6, CTA-lane
        // totals < 2^18 -> exact; planes 0-1 within existing noise budget.
        atomicAdd(&lane_sum[p0 & 3], acc0);
        atomicAdd(&lane_sum[(p0 & 3) + 1], acc1);
    }

    // ---- per-CTA flush ----
    __syncthreads();
    if (tid < 4) atomicAdd(&g_lane[tid], (double)lane_sum[tid]);
    for (int k = tid; k < CB_K; k += THREADS) {
        int cth = hist[k];
        if (cth) atomicAdd(&g_counts[k], cth);
    }

    // ---- last-CTA finalize + self-reset (graph-replay deterministic) ----
    __shared__ unsigned is_last;
    __threadfence();
    if (tid == 0) is_last = (atomicAdd(&g_ticket, 1u) == NCTAS - 1u) ? 1u : 0u;
    __syncthreads();
    if (is_last) {
        __threadfence();
        double e = 0.0;
        for (int k = tid; k < CB_K; k += THREADS) {
            int c = g_counts[k];
            if (c) { double p = (double)c / (double)N_PIX; e -= p * log2(p); }
            g_counts[k] = 0;
        }
        double* red = (double*)smem;   // es region dead; 16B-aligned
        red[tid] = e;
        __syncthreads();
        for (int o = THREADS / 2; o > 0; o >>= 1) {
            if (tid < o) red[tid] += red[tid + o];
            __syncthreads();
        }
        if (tid == 0) {
            out[OFF_ENT] = (float)red[0];
            // NEON faddp horizontal reduce: (s0+s1) + (s2+s3), all fp32.
            float s0 = (float)g_lane[0], s1 = (float)g_lane[1];
            float s2 = (float)g_lane[2], s3 = (float)g_lane[3];
            float hs = __fadd_rn(__fadd_rn(s0, s1), __fadd_rn(s2, s3));
            float L  = hs * (1.f / 33554432.f);
            out[OFF_LOSS] = __fadd_rn(L, 0.25f * L);
            g_lane[0] = 0.0; g_lane[1] = 0.0; g_lane[2] = 0.0; g_lane[3] = 0.0;
            g_ticket = 0u;
        }
    }
}

extern "C" void kernel_launch(void* const* d_in, const int* in_sizes, int n_in,
                              void* d_out, int out_size) {
    const float* x  = (const float*)d_in[0];
    const float* cb = (const float*)d_in[1];
    float* out = (float*)d_out;
    cudaFuncSetAttribute(vq_main, cudaFuncAttributeMaxDynamicSharedMemorySize, SMEM_BYTES);
    vq_main<<<NCTAS, THREADS, SMEM_BYTES>>>(x, cb, out);
}